// round 1
// baseline (speedup 1.0000x reference)
#include <cuda_runtime.h>
#include <cuda_bf16.h>

#define NN 50000
#define NE 1600000
#define F  128

// Scratch (device globals per harness rules)
__device__ float g_H[NN * F];            // 25.6 MB, fits in L2
__device__ int   g_row_start[NN + 1];
__device__ int   g_cursor[NN];
__device__ int   g_ecol[NE];
__device__ float g_eval[NE];

// ---------------------------------------------------------------------------
// CSR build: histogram -> scan -> scatter-permute (by destination row)
// ---------------------------------------------------------------------------
__global__ void k_zero_counts() {
    int i = blockIdx.x * blockDim.x + threadIdx.x;
    if (i <= NN) g_row_start[i] = 0;
}

__global__ void k_hist(const int* __restrict__ rows) {
    int i = blockIdx.x * blockDim.x + threadIdx.x;
    if (i < NE) atomicAdd(&g_row_start[rows[i]], 1);
}

// single-block scan over NN counters; 1024 threads, serial chunks + smem scan
__global__ void k_scan() {
    __shared__ int s[1024];
    const int C = (NN + 1023) / 1024;  // 49
    int t = threadIdx.x;
    int lo = t * C;
    int hi = min(lo + C, NN);
    int sum = 0;
    for (int i = lo; i < hi; i++) sum += g_row_start[i];
    s[t] = sum;
    __syncthreads();
    // Hillis-Steele inclusive scan
    for (int off = 1; off < 1024; off <<= 1) {
        int v = (t >= off) ? s[t - off] : 0;
        __syncthreads();
        s[t] += v;
        __syncthreads();
    }
    int run = (t == 0) ? 0 : s[t - 1];
    for (int i = lo; i < hi; i++) {
        int c = g_row_start[i];
        g_row_start[i] = run;
        g_cursor[i] = run;
        run += c;
    }
    if (t == 1023) g_row_start[NN] = NE;
}

__global__ void k_scatter(const float* __restrict__ vals,
                          const int* __restrict__ rows,
                          const int* __restrict__ cols) {
    int i = blockIdx.x * blockDim.x + threadIdx.x;
    if (i < NE) {
        int r = rows[i];
        int p = atomicAdd(&g_cursor[r], 1);
        g_ecol[p] = cols[i];
        g_eval[p] = vals[i];
    }
}

// ---------------------------------------------------------------------------
// SGEMM: H = X @ W^T.  Block computes 128 rows x 128 cols, thread 8x8 tile.
// K-tiles of 32, smem stored k-major (transposed) so inner reads are LDS.128.
// ---------------------------------------------------------------------------
__global__ void __launch_bounds__(256) k_gemm(const float* __restrict__ X,
                                              const float* __restrict__ W) {
    __shared__ __align__(16) float Xs[32][132];
    __shared__ __align__(16) float Ws[32][132];

    int tid = threadIdx.x;
    int row0 = blockIdx.x * 128;
    int tx = tid & 15;   // col group (8 cols)
    int ty = tid >> 4;   // row group (8 rows)

    float acc[8][8];
#pragma unroll
    for (int i = 0; i < 8; i++)
#pragma unroll
        for (int j = 0; j < 8; j++) acc[i][j] = 0.f;

    int lr = tid >> 1;          // 0..127 (row within tile)
    int lc = (tid & 1) * 16;    // 0 or 16 (k offset within k-tile)

    for (int k0 = 0; k0 < 128; k0 += 32) {
#pragma unroll
        for (int q = 0; q < 4; q++) {
            int k = lc + q * 4;
            int gr = row0 + lr;
            float4 xv = (gr < NN) ? *(const float4*)&X[gr * 128 + k0 + k]
                                  : make_float4(0.f, 0.f, 0.f, 0.f);
            Xs[k + 0][lr] = xv.x; Xs[k + 1][lr] = xv.y;
            Xs[k + 2][lr] = xv.z; Xs[k + 3][lr] = xv.w;
            float4 wv = *(const float4*)&W[lr * 128 + k0 + k];
            Ws[k + 0][lr] = wv.x; Ws[k + 1][lr] = wv.y;
            Ws[k + 2][lr] = wv.z; Ws[k + 3][lr] = wv.w;
        }
        __syncthreads();

#pragma unroll
        for (int kk = 0; kk < 32; kk++) {
            float4 xa = *(const float4*)&Xs[kk][ty * 8];
            float4 xb = *(const float4*)&Xs[kk][ty * 8 + 4];
            float4 wa = *(const float4*)&Ws[kk][tx * 8];
            float4 wb = *(const float4*)&Ws[kk][tx * 8 + 4];
            float x[8] = {xa.x, xa.y, xa.z, xa.w, xb.x, xb.y, xb.z, xb.w};
            float w[8] = {wa.x, wa.y, wa.z, wa.w, wb.x, wb.y, wb.z, wb.w};
#pragma unroll
            for (int i = 0; i < 8; i++)
#pragma unroll
                for (int j = 0; j < 8; j++) acc[i][j] += x[i] * w[j];
        }
        __syncthreads();
    }

#pragma unroll
    for (int i = 0; i < 8; i++) {
        int r = row0 + ty * 8 + i;
        if (r < NN) {
            int c = tx * 8;
            *(float4*)&g_H[r * 128 + c] =
                make_float4(acc[i][0], acc[i][1], acc[i][2], acc[i][3]);
            *(float4*)&g_H[r * 128 + c + 4] =
                make_float4(acc[i][4], acc[i][5], acc[i][6], acc[i][7]);
        }
    }
}

// ---------------------------------------------------------------------------
// SpMM: one warp per output row, lane owns 4 features (float4).
// Register accumulation, single streamed store per row — no float atomics.
// ---------------------------------------------------------------------------
__global__ void __launch_bounds__(256) k_spmm(float* __restrict__ out) {
    int warp = (blockIdx.x * blockDim.x + threadIdx.x) >> 5;
    int lane = threadIdx.x & 31;
    if (warp >= NN) return;

    int s = g_row_start[warp];
    int e = g_row_start[warp + 1];

    float4 acc = make_float4(0.f, 0.f, 0.f, 0.f);
    int i = s;
    // 2-deep software pipeline over edges for a bit of MLP
    for (; i + 1 < e; i += 2) {
        int   c0 = g_ecol[i];
        int   c1 = g_ecol[i + 1];
        float v0 = g_eval[i];
        float v1 = g_eval[i + 1];
        float4 h0 = *(const float4*)&g_H[c0 * F + lane * 4];
        float4 h1 = *(const float4*)&g_H[c1 * F + lane * 4];
        acc.x += v0 * h0.x; acc.y += v0 * h0.y;
        acc.z += v0 * h0.z; acc.w += v0 * h0.w;
        acc.x += v1 * h1.x; acc.y += v1 * h1.y;
        acc.z += v1 * h1.z; acc.w += v1 * h1.w;
    }
    if (i < e) {
        int   c0 = g_ecol[i];
        float v0 = g_eval[i];
        float4 h0 = *(const float4*)&g_H[c0 * F + lane * 4];
        acc.x += v0 * h0.x; acc.y += v0 * h0.y;
        acc.z += v0 * h0.z; acc.w += v0 * h0.w;
    }
    *(float4*)&out[warp * F + lane * 4] = acc;
}

// ---------------------------------------------------------------------------
extern "C" void kernel_launch(void* const* d_in, const int* in_sizes, int n_in,
                              void* d_out, int out_size) {
    const float* X     = (const float*)d_in[0];
    const float* W     = (const float*)d_in[1];
    const float* Avals = (const float*)d_in[2];
    const int*   Arows = (const int*)d_in[3];
    const int*   Acols = (const int*)d_in[4];
    float* out = (float*)d_out;

    // CSR build
    k_zero_counts<<<(NN + 1 + 255) / 256, 256>>>();
    k_hist<<<(NE + 255) / 256, 256>>>(Arows);
    k_scan<<<1, 1024>>>();
    k_scatter<<<(NE + 255) / 256, 256>>>(Avals, Arows, Acols);

    // Dense H = X @ W^T
    k_gemm<<<(NN + 127) / 128, 256>>>(X, W);

    // SpMM: out = A @ H
    k_spmm<<<(NN * 32 + 255) / 256, 256>>>(out);
}

// round 2
// speedup vs baseline: 1.1295x; 1.1295x over previous
#include <cuda_runtime.h>
#include <cuda_fp16.h>
#include <cuda_bf16.h>

#define NN 50000
#define NE 1600000
#define F  128

// Scratch (device globals per harness rules)
__device__ __half              g_H[NN * F];       // 12.8 MB, lives in L2
__device__ int                 g_row_start[NN + 1];
__device__ int                 g_cursor[NN];
__device__ unsigned long long  g_edge[NE];        // packed (col | val<<32)

// ---------------------------------------------------------------------------
// CSR build: histogram -> scan -> scatter-permute (by destination row)
// ---------------------------------------------------------------------------
__global__ void k_zero_counts() {
    int i = blockIdx.x * blockDim.x + threadIdx.x;
    if (i <= NN) g_row_start[i] = 0;
}

// 4 edges per thread, vectorized loads, independent atomics for MLP
__global__ void __launch_bounds__(256) k_hist(const int* __restrict__ rows) {
    int t = blockIdx.x * blockDim.x + threadIdx.x;
    int base = t * 4;
    if (base < NE) {
        int4 r = *(const int4*)&rows[base];
        atomicAdd(&g_row_start[r.x], 1);
        atomicAdd(&g_row_start[r.y], 1);
        atomicAdd(&g_row_start[r.z], 1);
        atomicAdd(&g_row_start[r.w], 1);
    }
}

// single-block scan over NN counters
__global__ void k_scan() {
    __shared__ int s[1024];
    const int C = (NN + 1023) / 1024;  // 49
    int t = threadIdx.x;
    int lo = t * C;
    int hi = min(lo + C, NN);
    int sum = 0;
    for (int i = lo; i < hi; i++) sum += g_row_start[i];
    s[t] = sum;
    __syncthreads();
    for (int off = 1; off < 1024; off <<= 1) {
        int v = (t >= off) ? s[t - off] : 0;
        __syncthreads();
        s[t] += v;
        __syncthreads();
    }
    int run = (t == 0) ? 0 : s[t - 1];
    for (int i = lo; i < hi; i++) {
        int c = g_row_start[i];
        g_row_start[i] = run;
        g_cursor[i] = run;
        run += c;
    }
    if (t == 1023) g_row_start[NN] = NE;
}

__device__ __forceinline__ unsigned long long pack_edge(int col, float val) {
    return (unsigned long long)(unsigned)col |
           ((unsigned long long)__float_as_uint(val) << 32);
}

// 4 edges per thread; packed 8B scattered stores (1 L2 sector each)
__global__ void __launch_bounds__(256) k_scatter(const float* __restrict__ vals,
                                                 const int* __restrict__ rows,
                                                 const int* __restrict__ cols) {
    int t = blockIdx.x * blockDim.x + threadIdx.x;
    int base = t * 4;
    if (base < NE) {
        int4   r = *(const int4*)&rows[base];
        int4   c = *(const int4*)&cols[base];
        float4 v = *(const float4*)&vals[base];
        int p0 = atomicAdd(&g_cursor[r.x], 1);
        int p1 = atomicAdd(&g_cursor[r.y], 1);
        int p2 = atomicAdd(&g_cursor[r.z], 1);
        int p3 = atomicAdd(&g_cursor[r.w], 1);
        g_edge[p0] = pack_edge(c.x, v.x);
        g_edge[p1] = pack_edge(c.y, v.y);
        g_edge[p2] = pack_edge(c.z, v.z);
        g_edge[p3] = pack_edge(c.w, v.w);
    }
}

// ---------------------------------------------------------------------------
// SGEMM: H = X @ W^T, fp32 compute, fp16 store.
// Block = 128 rows x 128 cols, thread 8x8 tile, k-major smem.
// ---------------------------------------------------------------------------
__global__ void __launch_bounds__(256) k_gemm(const float* __restrict__ X,
                                              const float* __restrict__ W) {
    __shared__ __align__(16) float Xs[32][132];
    __shared__ __align__(16) float Ws[32][132];

    int tid = threadIdx.x;
    int row0 = blockIdx.x * 128;
    int tx = tid & 15;
    int ty = tid >> 4;

    float acc[8][8];
#pragma unroll
    for (int i = 0; i < 8; i++)
#pragma unroll
        for (int j = 0; j < 8; j++) acc[i][j] = 0.f;

    int lr = tid >> 1;
    int lc = (tid & 1) * 16;

    for (int k0 = 0; k0 < 128; k0 += 32) {
#pragma unroll
        for (int q = 0; q < 4; q++) {
            int k = lc + q * 4;
            int gr = row0 + lr;
            float4 xv = (gr < NN) ? *(const float4*)&X[gr * 128 + k0 + k]
                                  : make_float4(0.f, 0.f, 0.f, 0.f);
            Xs[k + 0][lr] = xv.x; Xs[k + 1][lr] = xv.y;
            Xs[k + 2][lr] = xv.z; Xs[k + 3][lr] = xv.w;
            float4 wv = *(const float4*)&W[lr * 128 + k0 + k];
            Ws[k + 0][lr] = wv.x; Ws[k + 1][lr] = wv.y;
            Ws[k + 2][lr] = wv.z; Ws[k + 3][lr] = wv.w;
        }
        __syncthreads();

#pragma unroll
        for (int kk = 0; kk < 32; kk++) {
            float4 xa = *(const float4*)&Xs[kk][ty * 8];
            float4 xb = *(const float4*)&Xs[kk][ty * 8 + 4];
            float4 wa = *(const float4*)&Ws[kk][tx * 8];
            float4 wb = *(const float4*)&Ws[kk][tx * 8 + 4];
            float x[8] = {xa.x, xa.y, xa.z, xa.w, xb.x, xb.y, xb.z, xb.w};
            float w[8] = {wa.x, wa.y, wa.z, wa.w, wb.x, wb.y, wb.z, wb.w};
#pragma unroll
            for (int i = 0; i < 8; i++)
#pragma unroll
                for (int j = 0; j < 8; j++) acc[i][j] += x[i] * w[j];
        }
        __syncthreads();
    }

#pragma unroll
    for (int i = 0; i < 8; i++) {
        int r = row0 + ty * 8 + i;
        if (r < NN) {
            int c = tx * 8;
            __half2 h0 = __floats2half2_rn(acc[i][0], acc[i][1]);
            __half2 h1 = __floats2half2_rn(acc[i][2], acc[i][3]);
            __half2 h2 = __floats2half2_rn(acc[i][4], acc[i][5]);
            __half2 h3 = __floats2half2_rn(acc[i][6], acc[i][7]);
            uint2 pk0, pk1;
            pk0.x = *(unsigned*)&h0; pk0.y = *(unsigned*)&h1;
            pk1.x = *(unsigned*)&h2; pk1.y = *(unsigned*)&h3;
            *(uint2*)&g_H[r * 128 + c]     = pk0;
            *(uint2*)&g_H[r * 128 + c + 4] = pk1;
        }
    }
}

// ---------------------------------------------------------------------------
// SpMM: one warp per output row, lane owns 4 fp16 features (8B gather).
// fp32 accumulation, 4-deep unroll for MLP, one streamed float4 store/row.
// ---------------------------------------------------------------------------
__device__ __forceinline__ void acc_edge(float acc[4], unsigned long long pk,
                                         int lane) {
    int   c = (int)(unsigned)pk;
    float v = __uint_as_float((unsigned)(pk >> 32));
    uint2 hp = *(const uint2*)&g_H[c * F + lane * 4];
    float2 f0 = __half22float2(*(__half2*)&hp.x);
    float2 f1 = __half22float2(*(__half2*)&hp.y);
    acc[0] += v * f0.x; acc[1] += v * f0.y;
    acc[2] += v * f1.x; acc[3] += v * f1.y;
}

__global__ void __launch_bounds__(256) k_spmm(float* __restrict__ out) {
    int warp = (blockIdx.x * blockDim.x + threadIdx.x) >> 5;
    int lane = threadIdx.x & 31;
    if (warp >= NN) return;

    int s = g_row_start[warp];
    int e = g_row_start[warp + 1];

    float acc[4] = {0.f, 0.f, 0.f, 0.f};
    int i = s;
    for (; i + 3 < e; i += 4) {
        unsigned long long p0 = g_edge[i];
        unsigned long long p1 = g_edge[i + 1];
        unsigned long long p2 = g_edge[i + 2];
        unsigned long long p3 = g_edge[i + 3];
        acc_edge(acc, p0, lane);
        acc_edge(acc, p1, lane);
        acc_edge(acc, p2, lane);
        acc_edge(acc, p3, lane);
    }
    for (; i < e; i++) acc_edge(acc, g_edge[i], lane);

    *(float4*)&out[warp * F + lane * 4] =
        make_float4(acc[0], acc[1], acc[2], acc[3]);
}

// ---------------------------------------------------------------------------
extern "C" void kernel_launch(void* const* d_in, const int* in_sizes, int n_in,
                              void* d_out, int out_size) {
    const float* X     = (const float*)d_in[0];
    const float* W     = (const float*)d_in[1];
    const float* Avals = (const float*)d_in[2];
    const int*   Arows = (const int*)d_in[3];
    const int*   Acols = (const int*)d_in[4];
    float* out = (float*)d_out;

    // CSR build
    k_zero_counts<<<(NN + 1 + 255) / 256, 256>>>();
    k_hist<<<(NE / 4 + 255) / 256, 256>>>(Arows);
    k_scan<<<1, 1024>>>();
    k_scatter<<<(NE / 4 + 255) / 256, 256>>>(Avals, Arows, Acols);

    // Dense H = X @ W^T (fp32 compute, fp16 store)
    k_gemm<<<(NN + 127) / 128, 256>>>(X, W);

    // SpMM: out = A @ H
    k_spmm<<<(NN * 32 + 255) / 256, 256>>>(out);
}

// round 3
// speedup vs baseline: 1.6563x; 1.4664x over previous
#include <cuda_runtime.h>
#include <cuda_fp16.h>
#include <cuda_bf16.h>

#define NN 50000
#define NE 1600000
#define F  128

#define SCAN_BS 1024
#define SCAN_NB ((NN + SCAN_BS - 1) / SCAN_BS)   // 49

// Scratch (device globals per harness rules)
__device__ __half                           g_H[NN * F];   // 12.8 MB, lives in L2
__device__ int                              g_row_start[NN + 1];
__device__ int                              g_cursor[NN];
__device__ int                              g_px[NN];
__device__ int                              g_bsum[64];
__device__ __align__(16) unsigned long long g_edge[NE];    // packed (col | val<<32)

// ---------------------------------------------------------------------------
// CSR build: histogram -> 3-phase parallel scan -> scatter-permute
// ---------------------------------------------------------------------------
__global__ void __launch_bounds__(256) k_hist(const int* __restrict__ rows) {
    int t = blockIdx.x * blockDim.x + threadIdx.x;
    int base = t * 4;
    if (base < NE) {
        int4 r = *(const int4*)&rows[base];
        atomicAdd(&g_row_start[r.x], 1);
        atomicAdd(&g_row_start[r.y], 1);
        atomicAdd(&g_row_start[r.z], 1);
        atomicAdd(&g_row_start[r.w], 1);
    }
}

// Phase 1: per-block exclusive scan of counts, block totals to g_bsum
__global__ void __launch_bounds__(SCAN_BS) k_scan1() {
    __shared__ int s[SCAN_BS];
    int t = threadIdx.x;
    int i = blockIdx.x * SCAN_BS + t;
    int v = (i < NN) ? g_row_start[i] : 0;
    s[t] = v;
    __syncthreads();
#pragma unroll
    for (int off = 1; off < SCAN_BS; off <<= 1) {
        int u = (t >= off) ? s[t - off] : 0;
        __syncthreads();
        s[t] += u;
        __syncthreads();
    }
    if (i < NN) g_px[i] = s[t] - v;  // exclusive within block
    if (t == SCAN_BS - 1) g_bsum[blockIdx.x] = s[SCAN_BS - 1];
}

// Phase 2: single small block scans the 49 block sums (exclusive)
__global__ void k_scan2() {
    __shared__ int s[64];
    int t = threadIdx.x;
    int v = (t < SCAN_NB) ? g_bsum[t] : 0;
    s[t] = v;
    __syncthreads();
#pragma unroll
    for (int off = 1; off < 64; off <<= 1) {
        int u = (t >= off) ? s[t - off] : 0;
        __syncthreads();
        s[t] += u;
        __syncthreads();
    }
    if (t < SCAN_NB) g_bsum[t] = s[t] - v;  // exclusive
}

// Phase 3: combine -> row_start / cursor
__global__ void __launch_bounds__(SCAN_BS) k_scan3() {
    int i = blockIdx.x * SCAN_BS + threadIdx.x;
    if (i < NN) {
        int r = g_px[i] + g_bsum[blockIdx.x];
        g_row_start[i] = r;
        g_cursor[i] = r;
    }
    if (i == NN) g_row_start[NN] = NE;
}

__device__ __forceinline__ unsigned long long pack_edge(int col, float val) {
    return (unsigned long long)(unsigned)col |
           ((unsigned long long)__float_as_uint(val) << 32);
}

__global__ void __launch_bounds__(256) k_scatter(const float* __restrict__ vals,
                                                 const int* __restrict__ rows,
                                                 const int* __restrict__ cols) {
    int t = blockIdx.x * blockDim.x + threadIdx.x;
    int base = t * 4;
    if (base < NE) {
        int4   r = *(const int4*)&rows[base];
        int4   c = *(const int4*)&cols[base];
        float4 v = *(const float4*)&vals[base];
        int p0 = atomicAdd(&g_cursor[r.x], 1);
        int p1 = atomicAdd(&g_cursor[r.y], 1);
        int p2 = atomicAdd(&g_cursor[r.z], 1);
        int p3 = atomicAdd(&g_cursor[r.w], 1);
        g_edge[p0] = pack_edge(c.x, v.x);
        g_edge[p1] = pack_edge(c.y, v.y);
        g_edge[p2] = pack_edge(c.z, v.z);
        g_edge[p3] = pack_edge(c.w, v.w);
    }
}

// ---------------------------------------------------------------------------
// SGEMM: H = X @ W^T, fp32 compute, fp16 store.
// ---------------------------------------------------------------------------
__global__ void __launch_bounds__(256) k_gemm(const float* __restrict__ X,
                                              const float* __restrict__ W) {
    __shared__ __align__(16) float Xs[32][132];
    __shared__ __align__(16) float Ws[32][132];

    int tid = threadIdx.x;
    int row0 = blockIdx.x * 128;
    int tx = tid & 15;
    int ty = tid >> 4;

    float acc[8][8];
#pragma unroll
    for (int i = 0; i < 8; i++)
#pragma unroll
        for (int j = 0; j < 8; j++) acc[i][j] = 0.f;

    int lr = tid >> 1;
    int lc = (tid & 1) * 16;

    for (int k0 = 0; k0 < 128; k0 += 32) {
#pragma unroll
        for (int q = 0; q < 4; q++) {
            int k = lc + q * 4;
            int gr = row0 + lr;
            float4 xv = (gr < NN) ? *(const float4*)&X[gr * 128 + k0 + k]
                                  : make_float4(0.f, 0.f, 0.f, 0.f);
            Xs[k + 0][lr] = xv.x; Xs[k + 1][lr] = xv.y;
            Xs[k + 2][lr] = xv.z; Xs[k + 3][lr] = xv.w;
            float4 wv = *(const float4*)&W[lr * 128 + k0 + k];
            Ws[k + 0][lr] = wv.x; Ws[k + 1][lr] = wv.y;
            Ws[k + 2][lr] = wv.z; Ws[k + 3][lr] = wv.w;
        }
        __syncthreads();

#pragma unroll
        for (int kk = 0; kk < 32; kk++) {
            float4 xa = *(const float4*)&Xs[kk][ty * 8];
            float4 xb = *(const float4*)&Xs[kk][ty * 8 + 4];
            float4 wa = *(const float4*)&Ws[kk][tx * 8];
            float4 wb = *(const float4*)&Ws[kk][tx * 8 + 4];
            float x[8] = {xa.x, xa.y, xa.z, xa.w, xb.x, xb.y, xb.z, xb.w};
            float w[8] = {wa.x, wa.y, wa.z, wa.w, wb.x, wb.y, wb.z, wb.w};
#pragma unroll
            for (int i = 0; i < 8; i++)
#pragma unroll
                for (int j = 0; j < 8; j++) acc[i][j] += x[i] * w[j];
        }
        __syncthreads();
    }

#pragma unroll
    for (int i = 0; i < 8; i++) {
        int r = row0 + ty * 8 + i;
        if (r < NN) {
            int c = tx * 8;
            __half2 h0 = __floats2half2_rn(acc[i][0], acc[i][1]);
            __half2 h1 = __floats2half2_rn(acc[i][2], acc[i][3]);
            __half2 h2 = __floats2half2_rn(acc[i][4], acc[i][5]);
            __half2 h3 = __floats2half2_rn(acc[i][6], acc[i][7]);
            uint2 pk0, pk1;
            pk0.x = *(unsigned*)&h0; pk0.y = *(unsigned*)&h1;
            pk1.x = *(unsigned*)&h2; pk1.y = *(unsigned*)&h3;
            *(uint2*)&g_H[r * 128 + c]     = pk0;
            *(uint2*)&g_H[r * 128 + c + 4] = pk1;
        }
    }
}

// ---------------------------------------------------------------------------
// SpMM: warp per row, lane owns 4 fp16 features (8B gather), fp32 accum.
// 16B-vectorized edge loads + 8-deep gather unroll for MLP.
// ---------------------------------------------------------------------------
__device__ __forceinline__ void acc_edge(float acc[4], unsigned long long pk,
                                         int lane) {
    int   c = (int)(unsigned)pk;
    float v = __uint_as_float((unsigned)(pk >> 32));
    uint2 hp = *(const uint2*)&g_H[c * F + lane * 4];
    float2 f0 = __half22float2(*(__half2*)&hp.x);
    float2 f1 = __half22float2(*(__half2*)&hp.y);
    acc[0] += v * f0.x; acc[1] += v * f0.y;
    acc[2] += v * f1.x; acc[3] += v * f1.y;
}

__global__ void __launch_bounds__(256) k_spmm(float* __restrict__ out) {
    int warp = (blockIdx.x * blockDim.x + threadIdx.x) >> 5;
    int lane = threadIdx.x & 31;
    if (warp >= NN) return;

    int s = g_row_start[warp];
    int e = g_row_start[warp + 1];

    float acc[4] = {0.f, 0.f, 0.f, 0.f};
    int i = s;

    // align to 16B for vector loads (g_edge is 16B-aligned, 8B elements)
    if (i < e && (i & 1)) {
        acc_edge(acc, g_edge[i], lane);
        i++;
    }
    for (; i + 7 < e; i += 8) {
        ulonglong2 e01 = *(const ulonglong2*)&g_edge[i];
        ulonglong2 e23 = *(const ulonglong2*)&g_edge[i + 2];
        ulonglong2 e45 = *(const ulonglong2*)&g_edge[i + 4];
        ulonglong2 e67 = *(const ulonglong2*)&g_edge[i + 6];
        acc_edge(acc, e01.x, lane); acc_edge(acc, e01.y, lane);
        acc_edge(acc, e23.x, lane); acc_edge(acc, e23.y, lane);
        acc_edge(acc, e45.x, lane); acc_edge(acc, e45.y, lane);
        acc_edge(acc, e67.x, lane); acc_edge(acc, e67.y, lane);
    }
    for (; i + 1 < e; i += 2) {
        ulonglong2 e01 = *(const ulonglong2*)&g_edge[i];
        acc_edge(acc, e01.x, lane); acc_edge(acc, e01.y, lane);
    }
    if (i < e) acc_edge(acc, g_edge[i], lane);

    *(float4*)&out[warp * F + lane * 4] =
        make_float4(acc[0], acc[1], acc[2], acc[3]);
}

// ---------------------------------------------------------------------------
extern "C" void kernel_launch(void* const* d_in, const int* in_sizes, int n_in,
                              void* d_out, int out_size) {
    const float* X     = (const float*)d_in[0];
    const float* W     = (const float*)d_in[1];
    const float* Avals = (const float*)d_in[2];
    const int*   Arows = (const int*)d_in[3];
    const int*   Acols = (const int*)d_in[4];
    float* out = (float*)d_out;

    // zero counters via capturable async memset (no kernel needed)
    void* rs_addr = nullptr;
    cudaGetSymbolAddress(&rs_addr, g_row_start);
    cudaMemsetAsync(rs_addr, 0, (NN + 1) * sizeof(int));

    // CSR build
    k_hist<<<(NE / 4 + 255) / 256, 256>>>(Arows);
    k_scan1<<<SCAN_NB, SCAN_BS>>>();
    k_scan2<<<1, 64>>>();
    k_scan3<<<SCAN_NB + 1, SCAN_BS>>>();
    k_scatter<<<(NE / 4 + 255) / 256, 256>>>(Avals, Arows, Acols);

    // Dense H = X @ W^T (fp32 compute, fp16 store)
    k_gemm<<<(NN + 127) / 128, 256>>>(X, W);

    // SpMM: out = A @ H
    k_spmm<<<(NN * 32 + 255) / 256, 256>>>(out);
}

// round 4
// speedup vs baseline: 1.7789x; 1.0740x over previous
#include <cuda_runtime.h>
#include <cuda_fp16.h>
#include <cuda_bf16.h>

#define NN 50000
#define NE 1600000
#define F  128

#define SCAN_BS 1024
#define SCAN_NB ((NN + SCAN_BS - 1) / SCAN_BS)   // 49

#define G_HIST ((NE / 4 + 255) / 256)            // 1563 hist blocks
#define G_GEMM ((NN + 127) / 128)                // 391 gemm blocks

// Scratch (device globals per harness rules)
__device__ __half                           g_H[NN * F];   // 12.8 MB, lives in L2
__device__ int                              g_cnt[NN];     // zeroed per call
__device__ int                              g_row_start[NN + 1];
__device__ int                              g_px[NN];
__device__ int                              g_bsum[64];
__device__ int                              g_rank[NE];
__device__ __align__(16) unsigned long long g_edge[NE];    // packed (col | val<<32)

// ---------------------------------------------------------------------------
// Fused kernel: blocks [0, G_HIST) do the edge histogram (+rank), blocks
// [G_HIST, G_HIST+G_GEMM) do the dense GEMM H = X @ W^T (fp32->fp16).
// Hist is L2-atomic-latency-bound (issue ~2%), GEMM is FMA-bound; running
// them co-resident hides the hist latency under GEMM compute.
// ---------------------------------------------------------------------------
__global__ void __launch_bounds__(256) k_fused(const float* __restrict__ X,
                                               const float* __restrict__ W,
                                               const int* __restrict__ rows) {
    if (blockIdx.x < G_HIST) {
        // ----- histogram + rank assignment -----
        int t = blockIdx.x * 256 + threadIdx.x;
        int base = t * 4;
        if (base < NE) {
            int4 r = *(const int4*)&rows[base];
            int k0 = atomicAdd(&g_cnt[r.x], 1);
            int k1 = atomicAdd(&g_cnt[r.y], 1);
            int k2 = atomicAdd(&g_cnt[r.z], 1);
            int k3 = atomicAdd(&g_cnt[r.w], 1);
            *(int4*)&g_rank[base] = make_int4(k0, k1, k2, k3);
        }
        return;
    }

    // ----- GEMM: 128x128 block tile, 8x8 per-thread tile, k-major smem -----
    __shared__ __align__(16) float Xs[32][132];
    __shared__ __align__(16) float Ws[32][132];

    int tid = threadIdx.x;
    int row0 = (blockIdx.x - G_HIST) * 128;
    int tx = tid & 15;
    int ty = tid >> 4;

    float acc[8][8];
#pragma unroll
    for (int i = 0; i < 8; i++)
#pragma unroll
        for (int j = 0; j < 8; j++) acc[i][j] = 0.f;

    int lr = tid >> 1;
    int lc = (tid & 1) * 16;

    for (int k0 = 0; k0 < 128; k0 += 32) {
#pragma unroll
        for (int q = 0; q < 4; q++) {
            int k = lc + q * 4;
            int gr = row0 + lr;
            float4 xv = (gr < NN) ? *(const float4*)&X[gr * 128 + k0 + k]
                                  : make_float4(0.f, 0.f, 0.f, 0.f);
            Xs[k + 0][lr] = xv.x; Xs[k + 1][lr] = xv.y;
            Xs[k + 2][lr] = xv.z; Xs[k + 3][lr] = xv.w;
            float4 wv = *(const float4*)&W[lr * 128 + k0 + k];
            Ws[k + 0][lr] = wv.x; Ws[k + 1][lr] = wv.y;
            Ws[k + 2][lr] = wv.z; Ws[k + 3][lr] = wv.w;
        }
        __syncthreads();

#pragma unroll
        for (int kk = 0; kk < 32; kk++) {
            float4 xa = *(const float4*)&Xs[kk][ty * 8];
            float4 xb = *(const float4*)&Xs[kk][ty * 8 + 4];
            float4 wa = *(const float4*)&Ws[kk][tx * 8];
            float4 wb = *(const float4*)&Ws[kk][tx * 8 + 4];
            float x[8] = {xa.x, xa.y, xa.z, xa.w, xb.x, xb.y, xb.z, xb.w};
            float w[8] = {wa.x, wa.y, wa.z, wa.w, wb.x, wb.y, wb.z, wb.w};
#pragma unroll
            for (int i = 0; i < 8; i++)
#pragma unroll
                for (int j = 0; j < 8; j++) acc[i][j] += x[i] * w[j];
        }
        __syncthreads();
    }

#pragma unroll
    for (int i = 0; i < 8; i++) {
        int r = row0 + ty * 8 + i;
        if (r < NN) {
            int c = tx * 8;
            __half2 h0 = __floats2half2_rn(acc[i][0], acc[i][1]);
            __half2 h1 = __floats2half2_rn(acc[i][2], acc[i][3]);
            __half2 h2 = __floats2half2_rn(acc[i][4], acc[i][5]);
            __half2 h3 = __floats2half2_rn(acc[i][6], acc[i][7]);
            uint2 pk0, pk1;
            pk0.x = *(unsigned*)&h0; pk0.y = *(unsigned*)&h1;
            pk1.x = *(unsigned*)&h2; pk1.y = *(unsigned*)&h3;
            *(uint2*)&g_H[r * 128 + c]     = pk0;
            *(uint2*)&g_H[r * 128 + c + 4] = pk1;
        }
    }
}

// ---------------------------------------------------------------------------
// Scan phase 1: per-block exclusive scan of counts; block totals to g_bsum
// ---------------------------------------------------------------------------
__global__ void __launch_bounds__(SCAN_BS) k_scan1() {
    __shared__ int s[SCAN_BS];
    int t = threadIdx.x;
    int i = blockIdx.x * SCAN_BS + t;
    int v = (i < NN) ? g_cnt[i] : 0;
    s[t] = v;
    __syncthreads();
#pragma unroll
    for (int off = 1; off < SCAN_BS; off <<= 1) {
        int u = (t >= off) ? s[t - off] : 0;
        __syncthreads();
        s[t] += u;
        __syncthreads();
    }
    if (i < NN) g_px[i] = s[t] - v;  // exclusive within block
    if (t == SCAN_BS - 1) g_bsum[blockIdx.x] = s[SCAN_BS - 1];
}

// Scan phase 2+3 fused: every block redundantly scans the 49 block sums in
// smem (trivial), then writes final row_start.
__global__ void __launch_bounds__(SCAN_BS) k_scan3() {
    __shared__ int s[64];
    int t = threadIdx.x;
    if (t < 64) {
        int v = (t < SCAN_NB) ? g_bsum[t] : 0;
        s[t] = v;
    }
    __syncthreads();
    if (t < 64) {
#pragma unroll
        for (int off = 1; off < 64; off <<= 1) {
            int u = (t >= off) ? s[t - off] : 0;
            __syncwarp();  // 64 threads = 2 warps; need block sync actually
        }
    }
    // redo safely with simple serial scan by thread 0 (49 values, negligible)
    __syncthreads();
    if (t == 0) {
        int run = 0;
        for (int b = 0; b < SCAN_NB; b++) {
            int c = s[b];
            s[b] = run;
            run += c;
        }
    }
    __syncthreads();

    int i = blockIdx.x * SCAN_BS + t;
    if (i < NN) g_row_start[i] = g_px[i] + s[blockIdx.x];
    if (i == NN) g_row_start[NN] = NE;
}

// ---------------------------------------------------------------------------
// Scatter: atomic-free. pos = row_start[row] + rank. Pure streaming loads +
// fire-and-forget scattered 8B stores.
// ---------------------------------------------------------------------------
__device__ __forceinline__ unsigned long long pack_edge(int col, float val) {
    return (unsigned long long)(unsigned)col |
           ((unsigned long long)__float_as_uint(val) << 32);
}

__global__ void __launch_bounds__(256) k_scatter(const float* __restrict__ vals,
                                                 const int* __restrict__ rows,
                                                 const int* __restrict__ cols) {
    int t = blockIdx.x * blockDim.x + threadIdx.x;
    int base = t * 4;
    if (base < NE) {
        int4   r = *(const int4*)&rows[base];
        int4   c = *(const int4*)&cols[base];
        float4 v = *(const float4*)&vals[base];
        int4   k = *(const int4*)&g_rank[base];
        g_edge[g_row_start[r.x] + k.x] = pack_edge(c.x, v.x);
        g_edge[g_row_start[r.y] + k.y] = pack_edge(c.y, v.y);
        g_edge[g_row_start[r.z] + k.z] = pack_edge(c.z, v.z);
        g_edge[g_row_start[r.w] + k.w] = pack_edge(c.w, v.w);
    }
}

// ---------------------------------------------------------------------------
// SpMM: warp per row, lane owns 4 fp16 features (8B gather), fp32 accum.
// 16B-vectorized edge loads + 8-deep gather unroll for MLP.
// ---------------------------------------------------------------------------
__device__ __forceinline__ void acc_edge(float acc[4], unsigned long long pk,
                                         int lane) {
    int   c = (int)(unsigned)pk;
    float v = __uint_as_float((unsigned)(pk >> 32));
    uint2 hp = *(const uint2*)&g_H[c * F + lane * 4];
    float2 f0 = __half22float2(*(__half2*)&hp.x);
    float2 f1 = __half22float2(*(__half2*)&hp.y);
    acc[0] += v * f0.x; acc[1] += v * f0.y;
    acc[2] += v * f1.x; acc[3] += v * f1.y;
}

__global__ void __launch_bounds__(256) k_spmm(float* __restrict__ out) {
    int warp = (blockIdx.x * blockDim.x + threadIdx.x) >> 5;
    int lane = threadIdx.x & 31;
    if (warp >= NN) return;

    int s = g_row_start[warp];
    int e = g_row_start[warp + 1];

    float acc[4] = {0.f, 0.f, 0.f, 0.f};
    int i = s;

    // align to 16B for vector loads (g_edge is 16B-aligned, 8B elements)
    if (i < e && (i & 1)) {
        acc_edge(acc, g_edge[i], lane);
        i++;
    }
    for (; i + 7 < e; i += 8) {
        ulonglong2 e01 = *(const ulonglong2*)&g_edge[i];
        ulonglong2 e23 = *(const ulonglong2*)&g_edge[i + 2];
        ulonglong2 e45 = *(const ulonglong2*)&g_edge[i + 4];
        ulonglong2 e67 = *(const ulonglong2*)&g_edge[i + 6];
        acc_edge(acc, e01.x, lane); acc_edge(acc, e01.y, lane);
        acc_edge(acc, e23.x, lane); acc_edge(acc, e23.y, lane);
        acc_edge(acc, e45.x, lane); acc_edge(acc, e45.y, lane);
        acc_edge(acc, e67.x, lane); acc_edge(acc, e67.y, lane);
    }
    for (; i + 1 < e; i += 2) {
        ulonglong2 e01 = *(const ulonglong2*)&g_edge[i];
        acc_edge(acc, e01.x, lane); acc_edge(acc, e01.y, lane);
    }
    if (i < e) acc_edge(acc, g_edge[i], lane);

    *(float4*)&out[warp * F + lane * 4] =
        make_float4(acc[0], acc[1], acc[2], acc[3]);
}

// ---------------------------------------------------------------------------
extern "C" void kernel_launch(void* const* d_in, const int* in_sizes, int n_in,
                              void* d_out, int out_size) {
    const float* X     = (const float*)d_in[0];
    const float* W     = (const float*)d_in[1];
    const float* Avals = (const float*)d_in[2];
    const int*   Arows = (const int*)d_in[3];
    const int*   Acols = (const int*)d_in[4];
    float* out = (float*)d_out;

    // zero edge counters (capturable async memset)
    void* cnt_addr = nullptr;
    cudaGetSymbolAddress(&cnt_addr, g_cnt);
    cudaMemsetAsync(cnt_addr, 0, NN * sizeof(int));

    // fused: histogram(+rank) and dense GEMM co-resident
    k_fused<<<G_HIST + G_GEMM, 256>>>(X, W, Arows);

    // prefix scan -> row_start
    k_scan1<<<SCAN_NB, SCAN_BS>>>();
    k_scan3<<<SCAN_NB + 1, SCAN_BS>>>();

    // atomic-free scatter-permute
    k_scatter<<<(NE / 4 + 255) / 256, 256>>>(Avals, Arows, Acols);

    // SpMM: out = A @ H
    k_spmm<<<(NN * 32 + 255) / 256, 256>>>(out);
}

// round 6
// speedup vs baseline: 2.1844x; 1.2279x over previous
#include <cuda_runtime.h>
#include <cuda_fp16.h>
#include <cuda_bf16.h>
#include <mma.h>

using namespace nvcuda;

#define NN 50000
#define NE 1600000
#define F  128

#define SCAN_BS 1024
#define SCAN_NB ((NN + SCAN_BS - 1) / SCAN_BS)   // 49

// Scratch (device globals per harness rules)
__device__ __half                           g_H[NN * F];   // 12.8 MB, lives in L2
__device__ int                              g_cnt[NN];     // zeroed per call
__device__ int                              g_row_start[NN + 1];
__device__ int                              g_px[NN];
__device__ int                              g_bsum[64];
__device__ int                              g_rank[NE];
__device__ __align__(16) unsigned long long g_edge[NE];    // packed (col | val<<32)

// ---------------------------------------------------------------------------
// Histogram + rank: 8 edges per thread, 8 independent atomics for MLP
// ---------------------------------------------------------------------------
__global__ void __launch_bounds__(256) k_hist(const int* __restrict__ rows) {
    int t = blockIdx.x * blockDim.x + threadIdx.x;
    int base = t * 8;
    if (base < NE) {
        int4 r0 = *(const int4*)&rows[base];
        int4 r1 = *(const int4*)&rows[base + 4];
        int4 k0, k1;
        k0.x = atomicAdd(&g_cnt[r0.x], 1);
        k0.y = atomicAdd(&g_cnt[r0.y], 1);
        k0.z = atomicAdd(&g_cnt[r0.z], 1);
        k0.w = atomicAdd(&g_cnt[r0.w], 1);
        k1.x = atomicAdd(&g_cnt[r1.x], 1);
        k1.y = atomicAdd(&g_cnt[r1.y], 1);
        k1.z = atomicAdd(&g_cnt[r1.z], 1);
        k1.w = atomicAdd(&g_cnt[r1.w], 1);
        *(int4*)&g_rank[base]     = k0;
        *(int4*)&g_rank[base + 4] = k1;
    }
}

// ---------------------------------------------------------------------------
// GEMM via wmma (HMMA): H = X @ W^T, fp16 inputs (converted in-tile),
// fp32 accumulate, fp16 store. Block tile 128(M) x 128(N), K tiled by 64.
// ---------------------------------------------------------------------------
__global__ void __launch_bounds__(256) k_gemm(const float* __restrict__ X,
                                              const float* __restrict__ W) {
    __shared__ __align__(16) __half Xs[128][72];   // ld=72 halves (144B, mult of 16B)
    __shared__ __align__(16) __half Ws[128][72];
    __shared__ __align__(16) float  Stage[8][16][20];  // ld=20 floats (mult of 4!)

    int tid  = threadIdx.x;
    int warp = tid >> 5;
    int lane = tid & 31;
    int row0 = blockIdx.x * 128;

    wmma::fragment<wmma::accumulator, 16, 16, 16, float> c[8];
#pragma unroll
    for (int i = 0; i < 8; i++) wmma::fill_fragment(c[i], 0.0f);

    for (int kt = 0; kt < 2; kt++) {
        // load + convert X and W tiles (128 x 64 fp32 -> fp16)
#pragma unroll
        for (int it = 0; it < 16; it++) {
            int chunk = it * 256 + tid;        // 4096 float4-chunks per tile
            int r  = chunk >> 4;               // 0..255  (first 128 = X, next = W)
            int c4 = chunk & 15;
            if (r < 128) {
                int gr = row0 + r;
                float4 xv = (gr < NN) ? *(const float4*)&X[gr * 128 + kt * 64 + c4 * 4]
                                      : make_float4(0.f, 0.f, 0.f, 0.f);
                __half2 h0 = __floats2half2_rn(xv.x, xv.y);
                __half2 h1 = __floats2half2_rn(xv.z, xv.w);
                uint2 pk; pk.x = *(unsigned*)&h0; pk.y = *(unsigned*)&h1;
                *(uint2*)&Xs[r][c4 * 4] = pk;
            } else {
                int wr = r - 128;
                float4 wv = *(const float4*)&W[wr * 128 + kt * 64 + c4 * 4];
                __half2 h0 = __floats2half2_rn(wv.x, wv.y);
                __half2 h1 = __floats2half2_rn(wv.z, wv.w);
                uint2 pk; pk.x = *(unsigned*)&h0; pk.y = *(unsigned*)&h1;
                *(uint2*)&Ws[wr][c4 * 4] = pk;
            }
        }
        __syncthreads();

#pragma unroll
        for (int k0 = 0; k0 < 64; k0 += 16) {
            wmma::fragment<wmma::matrix_a, 16, 16, 16, __half, wmma::row_major> a;
            wmma::load_matrix_sync(a, &Xs[warp * 16][k0], 72);
#pragma unroll
            for (int n0 = 0; n0 < 8; n0++) {
                wmma::fragment<wmma::matrix_b, 16, 16, 16, __half, wmma::col_major> b;
                wmma::load_matrix_sync(b, &Ws[n0 * 16][k0], 72);
                wmma::mma_sync(c[n0], a, b, c[n0]);
            }
        }
        __syncthreads();
    }

    // epilogue: per-warp stage each 16x16 fragment, convert to fp16, store
    int r  = lane >> 1;
    int cg = (lane & 1) * 8;
    int gr = row0 + warp * 16 + r;
#pragma unroll
    for (int n0 = 0; n0 < 8; n0++) {
        wmma::store_matrix_sync(&Stage[warp][0][0], c[n0], 20, wmma::mem_row_major);
        __syncwarp();
        if (gr < NN) {
            const float* src = &Stage[warp][r][cg];
            __half2 h0 = __floats2half2_rn(src[0], src[1]);
            __half2 h1 = __floats2half2_rn(src[2], src[3]);
            __half2 h2 = __floats2half2_rn(src[4], src[5]);
            __half2 h3 = __floats2half2_rn(src[6], src[7]);
            uint4 pk;
            pk.x = *(unsigned*)&h0; pk.y = *(unsigned*)&h1;
            pk.z = *(unsigned*)&h2; pk.w = *(unsigned*)&h3;
            *(uint4*)&g_H[gr * 128 + n0 * 16 + cg] = pk;
        }
        __syncwarp();
    }
}

// ---------------------------------------------------------------------------
// Scan phase 1: per-block exclusive scan of counts; block totals to g_bsum
// ---------------------------------------------------------------------------
__global__ void __launch_bounds__(SCAN_BS) k_scan1() {
    __shared__ int s[SCAN_BS];
    int t = threadIdx.x;
    int i = blockIdx.x * SCAN_BS + t;
    int v = (i < NN) ? g_cnt[i] : 0;
    s[t] = v;
    __syncthreads();
#pragma unroll
    for (int off = 1; off < SCAN_BS; off <<= 1) {
        int u = (t >= off) ? s[t - off] : 0;
        __syncthreads();
        s[t] += u;
        __syncthreads();
    }
    if (i < NN) g_px[i] = s[t] - v;  // exclusive within block
    if (t == SCAN_BS - 1) g_bsum[blockIdx.x] = s[SCAN_BS - 1];
}

// Scan phase 2+3 fused: each block serially scans the 49 block sums (cheap),
// then writes final row_start.
__global__ void __launch_bounds__(SCAN_BS) k_scan3() {
    __shared__ int s[64];
    int t = threadIdx.x;
    if (t < SCAN_NB) s[t] = g_bsum[t];
    __syncthreads();
    if (t == 0) {
        int run = 0;
        for (int b = 0; b < SCAN_NB; b++) {
            int c = s[b];
            s[b] = run;
            run += c;
        }
    }
    __syncthreads();

    int i = blockIdx.x * SCAN_BS + t;
    if (i < NN) g_row_start[i] = g_px[i] + s[blockIdx.x];
    if (i == NN) g_row_start[NN] = NE;
}

// ---------------------------------------------------------------------------
// Scatter: atomic-free, 8 edges/thread. pos = row_start[row] + rank.
// ---------------------------------------------------------------------------
__device__ __forceinline__ unsigned long long pack_edge(int col, float val) {
    return (unsigned long long)(unsigned)col |
           ((unsigned long long)__float_as_uint(val) << 32);
}

__global__ void __launch_bounds__(256) k_scatter(const float* __restrict__ vals,
                                                 const int* __restrict__ rows,
                                                 const int* __restrict__ cols) {
    int t = blockIdx.x * blockDim.x + threadIdx.x;
    int base = t * 8;
    if (base < NE) {
        int4   r0 = *(const int4*)&rows[base];
        int4   r1 = *(const int4*)&rows[base + 4];
        int4   c0 = *(const int4*)&cols[base];
        int4   c1 = *(const int4*)&cols[base + 4];
        float4 v0 = *(const float4*)&vals[base];
        float4 v1 = *(const float4*)&vals[base + 4];
        int4   k0 = *(const int4*)&g_rank[base];
        int4   k1 = *(const int4*)&g_rank[base + 4];
        int p0 = g_row_start[r0.x] + k0.x;
        int p1 = g_row_start[r0.y] + k0.y;
        int p2 = g_row_start[r0.z] + k0.z;
        int p3 = g_row_start[r0.w] + k0.w;
        int p4 = g_row_start[r1.x] + k1.x;
        int p5 = g_row_start[r1.y] + k1.y;
        int p6 = g_row_start[r1.z] + k1.z;
        int p7 = g_row_start[r1.w] + k1.w;
        g_edge[p0] = pack_edge(c0.x, v0.x);
        g_edge[p1] = pack_edge(c0.y, v0.y);
        g_edge[p2] = pack_edge(c0.z, v0.z);
        g_edge[p3] = pack_edge(c0.w, v0.w);
        g_edge[p4] = pack_edge(c1.x, v1.x);
        g_edge[p5] = pack_edge(c1.y, v1.y);
        g_edge[p6] = pack_edge(c1.z, v1.z);
        g_edge[p7] = pack_edge(c1.w, v1.w);
    }
}

// ---------------------------------------------------------------------------
// SpMM: warp per row, lane owns 4 fp16 features (8B gather), fp32 accum.
// 16B-vectorized edge loads + 8-deep gather unroll for MLP.
// ---------------------------------------------------------------------------
__device__ __forceinline__ void acc_edge(float acc[4], unsigned long long pk,
                                         int lane) {
    int   c = (int)(unsigned)pk;
    float v = __uint_as_float((unsigned)(pk >> 32));
    uint2 hp = *(const uint2*)&g_H[c * F + lane * 4];
    float2 f0 = __half22float2(*(__half2*)&hp.x);
    float2 f1 = __half22float2(*(__half2*)&hp.y);
    acc[0] += v * f0.x; acc[1] += v * f0.y;
    acc[2] += v * f1.x; acc[3] += v * f1.y;
}

__global__ void __launch_bounds__(256) k_spmm(float* __restrict__ out) {
    int warp = (blockIdx.x * blockDim.x + threadIdx.x) >> 5;
    int lane = threadIdx.x & 31;
    if (warp >= NN) return;

    int s = g_row_start[warp];
    int e = g_row_start[warp + 1];

    float acc[4] = {0.f, 0.f, 0.f, 0.f};
    int i = s;

    if (i < e && (i & 1)) {
        acc_edge(acc, g_edge[i], lane);
        i++;
    }
    for (; i + 7 < e; i += 8) {
        ulonglong2 e01 = *(const ulonglong2*)&g_edge[i];
        ulonglong2 e23 = *(const ulonglong2*)&g_edge[i + 2];
        ulonglong2 e45 = *(const ulonglong2*)&g_edge[i + 4];
        ulonglong2 e67 = *(const ulonglong2*)&g_edge[i + 6];
        acc_edge(acc, e01.x, lane); acc_edge(acc, e01.y, lane);
        acc_edge(acc, e23.x, lane); acc_edge(acc, e23.y, lane);
        acc_edge(acc, e45.x, lane); acc_edge(acc, e45.y, lane);
        acc_edge(acc, e67.x, lane); acc_edge(acc, e67.y, lane);
    }
    for (; i + 1 < e; i += 2) {
        ulonglong2 e01 = *(const ulonglong2*)&g_edge[i];
        acc_edge(acc, e01.x, lane); acc_edge(acc, e01.y, lane);
    }
    if (i < e) acc_edge(acc, g_edge[i], lane);

    *(float4*)&out[warp * F + lane * 4] =
        make_float4(acc[0], acc[1], acc[2], acc[3]);
}

// ---------------------------------------------------------------------------
extern "C" void kernel_launch(void* const* d_in, const int* in_sizes, int n_in,
                              void* d_out, int out_size) {
    const float* X     = (const float*)d_in[0];
    const float* W     = (const float*)d_in[1];
    const float* Avals = (const float*)d_in[2];
    const int*   Arows = (const int*)d_in[3];
    const int*   Acols = (const int*)d_in[4];
    float* out = (float*)d_out;

    // zero edge counters (capturable async memset)
    void* cnt_addr = nullptr;
    cudaGetSymbolAddress(&cnt_addr, g_cnt);
    cudaMemsetAsync(cnt_addr, 0, NN * sizeof(int));

    // CSR build + dense GEMM
    k_hist<<<(NE / 8 + 255) / 256, 256>>>(Arows);
    k_gemm<<<(NN + 127) / 128, 256>>>(X, W);
    k_scan1<<<SCAN_NB, SCAN_BS>>>();
    k_scan3<<<SCAN_NB + 1, SCAN_BS>>>();
    k_scatter<<<(NE / 8 + 255) / 256, 256>>>(Avals, Arows, Acols);

    // SpMM: out = A @ H
    k_spmm<<<(NN * 32 + 255) / 256, 256>>>(out);
}

// round 7
// speedup vs baseline: 2.2732x; 1.0407x over previous
#include <cuda_runtime.h>
#include <cuda_fp16.h>
#include <cuda_bf16.h>
#include <mma.h>

using namespace nvcuda;

#define NN 50000
#define NE 1600000
#define F  128

#define SCAN_BS 1024
#define SCAN_NB ((NN + SCAN_BS - 1) / SCAN_BS)   // 49
#define FLAG    0x40000000

#define G_HIST ((NE / 8 + 255) / 256)            // 782 hist blocks
#define G_GEMM ((NN + 127) / 128)                // 391 gemm blocks

// Scratch (device globals per harness rules)
__device__ __half              g_H[NN * F];      // 12.8 MB, lives in L2
__device__ int                 g_cnt[NN + 64];   // counts + scan flags; zeroed per call
__device__ int                 g_row_start[NN + 1];
__device__ int                 g_rank[NE];
__device__ __align__(16) unsigned g_edge[NE];    // packed (col u16 | val-fp16 u16)

// ---------------------------------------------------------------------------
// Fused kernel: blocks [0, G_HIST) do histogram+rank (8 edges/thread, 8
// independent ATOMGs in flight); blocks [G_HIST, ..) do the HMMA GEMM.
// Hist is L2-atomic-latency-bound; GEMM is tensor-pipe-bound -> co-resident.
// ---------------------------------------------------------------------------
__global__ void __launch_bounds__(256) k_fused(const float* __restrict__ X,
                                               const float* __restrict__ W,
                                               const int* __restrict__ rows) {
    if (blockIdx.x < G_HIST) {
        int t = blockIdx.x * 256 + threadIdx.x;
        int base = t * 8;
        if (base < NE) {
            int4 r0 = *(const int4*)&rows[base];
            int4 r1 = *(const int4*)&rows[base + 4];
            int4 k0, k1;
            k0.x = atomicAdd(&g_cnt[r0.x], 1);
            k0.y = atomicAdd(&g_cnt[r0.y], 1);
            k0.z = atomicAdd(&g_cnt[r0.z], 1);
            k0.w = atomicAdd(&g_cnt[r0.w], 1);
            k1.x = atomicAdd(&g_cnt[r1.x], 1);
            k1.y = atomicAdd(&g_cnt[r1.y], 1);
            k1.z = atomicAdd(&g_cnt[r1.z], 1);
            k1.w = atomicAdd(&g_cnt[r1.w], 1);
            *(int4*)&g_rank[base]     = k0;
            *(int4*)&g_rank[base + 4] = k1;
        }
        return;
    }

    // ----- GEMM via wmma: H = X @ W^T, fp16 in, fp32 acc, fp16 out -----
    __shared__ __align__(16) __half Xs[128][72];
    __shared__ __align__(16) __half Ws[128][72];
    __shared__ __align__(16) float  Stage[8][16][20];  // ldm=20 (mult of 4)

    int tid  = threadIdx.x;
    int warp = tid >> 5;
    int lane = tid & 31;
    int row0 = (blockIdx.x - G_HIST) * 128;

    wmma::fragment<wmma::accumulator, 16, 16, 16, float> c[8];
#pragma unroll
    for (int i = 0; i < 8; i++) wmma::fill_fragment(c[i], 0.0f);

    for (int kt = 0; kt < 2; kt++) {
#pragma unroll
        for (int it = 0; it < 16; it++) {
            int chunk = it * 256 + tid;
            int r  = chunk >> 4;
            int c4 = chunk & 15;
            if (r < 128) {
                int gr = row0 + r;
                float4 xv = (gr < NN) ? *(const float4*)&X[gr * 128 + kt * 64 + c4 * 4]
                                      : make_float4(0.f, 0.f, 0.f, 0.f);
                __half2 h0 = __floats2half2_rn(xv.x, xv.y);
                __half2 h1 = __floats2half2_rn(xv.z, xv.w);
                uint2 pk; pk.x = *(unsigned*)&h0; pk.y = *(unsigned*)&h1;
                *(uint2*)&Xs[r][c4 * 4] = pk;
            } else {
                int wr = r - 128;
                float4 wv = *(const float4*)&W[wr * 128 + kt * 64 + c4 * 4];
                __half2 h0 = __floats2half2_rn(wv.x, wv.y);
                __half2 h1 = __floats2half2_rn(wv.z, wv.w);
                uint2 pk; pk.x = *(unsigned*)&h0; pk.y = *(unsigned*)&h1;
                *(uint2*)&Ws[wr][c4 * 4] = pk;
            }
        }
        __syncthreads();

#pragma unroll
        for (int k0 = 0; k0 < 64; k0 += 16) {
            wmma::fragment<wmma::matrix_a, 16, 16, 16, __half, wmma::row_major> a;
            wmma::load_matrix_sync(a, &Xs[warp * 16][k0], 72);
#pragma unroll
            for (int n0 = 0; n0 < 8; n0++) {
                wmma::fragment<wmma::matrix_b, 16, 16, 16, __half, wmma::col_major> b;
                wmma::load_matrix_sync(b, &Ws[n0 * 16][k0], 72);
                wmma::mma_sync(c[n0], a, b, c[n0]);
            }
        }
        __syncthreads();
    }

    int r  = lane >> 1;
    int cg = (lane & 1) * 8;
    int gr = row0 + warp * 16 + r;
#pragma unroll
    for (int n0 = 0; n0 < 8; n0++) {
        wmma::store_matrix_sync(&Stage[warp][0][0], c[n0], 20, wmma::mem_row_major);
        __syncwarp();
        if (gr < NN) {
            const float* src = &Stage[warp][r][cg];
            __half2 h0 = __floats2half2_rn(src[0], src[1]);
            __half2 h1 = __floats2half2_rn(src[2], src[3]);
            __half2 h2 = __floats2half2_rn(src[4], src[5]);
            __half2 h3 = __floats2half2_rn(src[6], src[7]);
            uint4 pk;
            pk.x = *(unsigned*)&h0; pk.y = *(unsigned*)&h1;
            pk.z = *(unsigned*)&h2; pk.w = *(unsigned*)&h3;
            *(uint4*)&g_H[gr * 128 + n0 * 16 + cg] = pk;
        }
        __syncwarp();
    }
}

// ---------------------------------------------------------------------------
// Single-kernel exclusive scan with parallel-lookback.
// 49 blocks (always co-resident on 148 SMs -> no deadlock). Each block:
// shuffle-scan its 1024 counts, publish aggregate (FLAG-tagged) via atomic,
// parallel-poll all predecessors' aggregates, write row_start directly.
// Flag words live in g_cnt[NN..NN+63] (zeroed by the per-call memset).
// ---------------------------------------------------------------------------
__global__ void __launch_bounds__(SCAN_BS) k_scan() {
    __shared__ int wsum[32];
    __shared__ int pred[64];
    __shared__ int spref;

    int t = threadIdx.x;
    int lane = t & 31;
    int wid = t >> 5;
    int i = blockIdx.x * SCAN_BS + t;
    int v = (i < NN) ? g_cnt[i] : 0;

    // warp inclusive scan
    int x = v;
#pragma unroll
    for (int o = 1; o < 32; o <<= 1) {
        int u = __shfl_up_sync(0xffffffffu, x, o);
        if (lane >= o) x += u;
    }
    if (lane == 31) wsum[wid] = x;
    __syncthreads();
    if (wid == 0) {
        int y = wsum[lane];
#pragma unroll
        for (int o = 1; o < 32; o <<= 1) {
            int u = __shfl_up_sync(0xffffffffu, y, o);
            if (lane >= o) y += u;
        }
        wsum[lane] = y;
    }
    __syncthreads();

    int incl = x + (wid ? wsum[wid - 1] : 0);
    int block_total = wsum[31];

    // publish this block's aggregate
    if (t == 0) atomicExch(&g_cnt[NN + blockIdx.x], block_total | FLAG);

    // gather predecessor aggregates (parallel poll)
    if (t < 64) pred[t] = 0;
    __syncthreads();
    if (t < blockIdx.x) {
        int val;
        do { val = atomicAdd(&g_cnt[NN + t], 0); } while (!(val & FLAG));
        pred[t] = val & ~FLAG;
    }
    __syncthreads();
    if (t == 0) {
        int run = 0;
        for (int b = 0; b < (int)blockIdx.x; b++) run += pred[b];
        spref = run;
    }
    __syncthreads();

    int excl = spref + incl - v;
    if (i < NN) g_row_start[i] = excl;
    if (i == NN) g_row_start[NN] = NE;
}

// ---------------------------------------------------------------------------
// Scatter: atomic-free, 8 edges/thread, 4B packed records
// (col u16 | fp16(val) u16). pos = row_start[row] + rank.
// ---------------------------------------------------------------------------
__device__ __forceinline__ unsigned pack_edge(int col, float val) {
    return (unsigned)col |
           ((unsigned)__half_as_ushort(__float2half_rn(val)) << 16);
}

__global__ void __launch_bounds__(256) k_scatter(const float* __restrict__ vals,
                                                 const int* __restrict__ rows,
                                                 const int* __restrict__ cols) {
    int t = blockIdx.x * blockDim.x + threadIdx.x;
    int base = t * 8;
    if (base < NE) {
        int4   r0 = *(const int4*)&rows[base];
        int4   r1 = *(const int4*)&rows[base + 4];
        int4   c0 = *(const int4*)&cols[base];
        int4   c1 = *(const int4*)&cols[base + 4];
        float4 v0 = *(const float4*)&vals[base];
        float4 v1 = *(const float4*)&vals[base + 4];
        int4   k0 = *(const int4*)&g_rank[base];
        int4   k1 = *(const int4*)&g_rank[base + 4];
        g_edge[g_row_start[r0.x] + k0.x] = pack_edge(c0.x, v0.x);
        g_edge[g_row_start[r0.y] + k0.y] = pack_edge(c0.y, v0.y);
        g_edge[g_row_start[r0.z] + k0.z] = pack_edge(c0.z, v0.z);
        g_edge[g_row_start[r0.w] + k0.w] = pack_edge(c0.w, v0.w);
        g_edge[g_row_start[r1.x] + k1.x] = pack_edge(c1.x, v1.x);
        g_edge[g_row_start[r1.y] + k1.y] = pack_edge(c1.y, v1.y);
        g_edge[g_row_start[r1.z] + k1.z] = pack_edge(c1.z, v1.z);
        g_edge[g_row_start[r1.w] + k1.w] = pack_edge(c1.w, v1.w);
    }
}

// ---------------------------------------------------------------------------
// SpMM: warp per row, lane owns 4 fp16 features (8B gather via __ldcg),
// fp32 accum, 16B-vectorized 4B-edge loads + 8-deep unroll.
// ---------------------------------------------------------------------------
__device__ __forceinline__ void acc_edge(float acc[4], unsigned pk, int lane) {
    int   c = (int)(pk & 0xFFFFu);
    float v = __half2float(__ushort_as_half((unsigned short)(pk >> 16)));
    uint2 hp = __ldcg((const uint2*)&g_H[c * F + lane * 4]);
    float2 f0 = __half22float2(*(__half2*)&hp.x);
    float2 f1 = __half22float2(*(__half2*)&hp.y);
    acc[0] += v * f0.x; acc[1] += v * f0.y;
    acc[2] += v * f1.x; acc[3] += v * f1.y;
}

__global__ void __launch_bounds__(256) k_spmm(float* __restrict__ out) {
    int warp = (blockIdx.x * blockDim.x + threadIdx.x) >> 5;
    int lane = threadIdx.x & 31;
    if (warp >= NN) return;

    int s = g_row_start[warp];
    int e = g_row_start[warp + 1];

    float acc[4] = {0.f, 0.f, 0.f, 0.f};
    int i = s;

    // align to 16B (4 records) for uint4 vector loads
    while (i < e && (i & 3)) {
        acc_edge(acc, g_edge[i], lane);
        i++;
    }
    for (; i + 7 < e; i += 8) {
        uint4 ea = *(const uint4*)&g_edge[i];
        uint4 eb = *(const uint4*)&g_edge[i + 4];
        acc_edge(acc, ea.x, lane); acc_edge(acc, ea.y, lane);
        acc_edge(acc, ea.z, lane); acc_edge(acc, ea.w, lane);
        acc_edge(acc, eb.x, lane); acc_edge(acc, eb.y, lane);
        acc_edge(acc, eb.z, lane); acc_edge(acc, eb.w, lane);
    }
    for (; i + 3 < e; i += 4) {
        uint4 ea = *(const uint4*)&g_edge[i];
        acc_edge(acc, ea.x, lane); acc_edge(acc, ea.y, lane);
        acc_edge(acc, ea.z, lane); acc_edge(acc, ea.w, lane);
    }
    for (; i < e; i++) acc_edge(acc, g_edge[i], lane);

    *(float4*)&out[warp * F + lane * 4] =
        make_float4(acc[0], acc[1], acc[2], acc[3]);
}

// ---------------------------------------------------------------------------
extern "C" void kernel_launch(void* const* d_in, const int* in_sizes, int n_in,
                              void* d_out, int out_size) {
    const float* X     = (const float*)d_in[0];
    const float* W     = (const float*)d_in[1];
    const float* Avals = (const float*)d_in[2];
    const int*   Arows = (const int*)d_in[3];
    const int*   Acols = (const int*)d_in[4];
    float* out = (float*)d_out;

    // zero edge counters + scan flags (capturable async memset)
    void* cnt_addr = nullptr;
    cudaGetSymbolAddress(&cnt_addr, g_cnt);
    cudaMemsetAsync(cnt_addr, 0, (NN + 64) * sizeof(int));

    // fused: histogram(+rank) co-resident with HMMA GEMM
    k_fused<<<G_HIST + G_GEMM, 256>>>(X, W, Arows);

    // one-shot prefix scan -> row_start
    k_scan<<<SCAN_NB, SCAN_BS>>>();

    // atomic-free scatter-permute into 4B records
    k_scatter<<<(NE / 8 + 255) / 256, 256>>>(Avals, Arows, Acols);

    // SpMM: out = A @ H
    k_spmm<<<(NN * 32 + 255) / 256, 256>>>(out);
}

// round 8
// speedup vs baseline: 2.6030x; 1.1451x over previous
#include <cuda_runtime.h>
#include <cuda_fp16.h>
#include <cuda_bf16.h>
#include <mma.h>

using namespace nvcuda;

#define NN 50000
#define NE 1600000
#define F  128

#define SCAN_BS 1024
#define SCAN_NB ((NN + SCAN_BS - 1) / SCAN_BS)   // 49
#define FLAG    0x40000000

#define G_HIST 782                               // = ceil(NE/8/256); == 2*G_GEMM
#define G_GEMM 391                               // = ceil(NN/128)

// Scratch (device globals per harness rules)
__device__ __half              g_H[NN * F];      // 12.8 MB, lives in L2
__device__ int                 g_cnt[NN + 64];   // counts + scan flags; zeroed per call
__device__ int                 g_row_start[NN + 1];
__device__ __align__(8) unsigned char g_rank[NE];  // u8 ranks (max degree << 255)
__device__ __align__(16) unsigned g_edge[NE];    // packed (col u16 | val-fp16 u16)

// ---------------------------------------------------------------------------
// Fused kernel, role-STRIPED so hist and gemm blocks co-reside in every wave:
//   blockIdx % 3 in {0,1} -> histogram+rank (latency-bound ATOMG work)
//   blockIdx % 3 == 2     -> HMMA GEMM      (tensor/issue-bound work)
// ---------------------------------------------------------------------------
__global__ void __launch_bounds__(256) k_fused(const float* __restrict__ X,
                                               const float* __restrict__ W,
                                               const int* __restrict__ rows) {
    int role = blockIdx.x % 3;
    int grp  = blockIdx.x / 3;

    if (role < 2) {
        // ----- histogram + u8 rank, 8 edges/thread, 8 ATOMGs in flight -----
        int hb = grp * 2 + role;                 // 0..781
        int t = hb * 256 + threadIdx.x;
        int base = t * 8;
        if (base < NE) {
            int4 r0 = *(const int4*)&rows[base];
            int4 r1 = *(const int4*)&rows[base + 4];
            unsigned k0 = (unsigned)atomicAdd(&g_cnt[r0.x], 1);
            unsigned k1 = (unsigned)atomicAdd(&g_cnt[r0.y], 1);
            unsigned k2 = (unsigned)atomicAdd(&g_cnt[r0.z], 1);
            unsigned k3 = (unsigned)atomicAdd(&g_cnt[r0.w], 1);
            unsigned k4 = (unsigned)atomicAdd(&g_cnt[r1.x], 1);
            unsigned k5 = (unsigned)atomicAdd(&g_cnt[r1.y], 1);
            unsigned k6 = (unsigned)atomicAdd(&g_cnt[r1.z], 1);
            unsigned k7 = (unsigned)atomicAdd(&g_cnt[r1.w], 1);
            unsigned lo = k0 | (k1 << 8) | (k2 << 16) | (k3 << 24);
            unsigned hi = k4 | (k5 << 8) | (k6 << 16) | (k7 << 24);
            *(uint2*)&g_rank[base] = make_uint2(lo, hi);
        }
        return;
    }

    // ----- GEMM via wmma: H = X @ W^T, fp16 in, fp32 acc, fp16 out -----
    __shared__ __align__(16) __half Xs[128][72];
    __shared__ __align__(16) __half Ws[128][72];
    __shared__ __align__(16) float  Stage[8][16][20];  // ldm=20 (mult of 4)

    int tid  = threadIdx.x;
    int warp = tid >> 5;
    int lane = tid & 31;
    int row0 = grp * 128;

    wmma::fragment<wmma::accumulator, 16, 16, 16, float> c[8];
#pragma unroll
    for (int i = 0; i < 8; i++) wmma::fill_fragment(c[i], 0.0f);

    for (int kt = 0; kt < 2; kt++) {
#pragma unroll
        for (int it = 0; it < 16; it++) {
            int chunk = it * 256 + tid;
            int r  = chunk >> 4;
            int c4 = chunk & 15;
            if (r < 128) {
                int gr = row0 + r;
                float4 xv = (gr < NN) ? *(const float4*)&X[gr * 128 + kt * 64 + c4 * 4]
                                      : make_float4(0.f, 0.f, 0.f, 0.f);
                __half2 h0 = __floats2half2_rn(xv.x, xv.y);
                __half2 h1 = __floats2half2_rn(xv.z, xv.w);
                uint2 pk; pk.x = *(unsigned*)&h0; pk.y = *(unsigned*)&h1;
                *(uint2*)&Xs[r][c4 * 4] = pk;
            } else {
                int wr = r - 128;
                float4 wv = *(const float4*)&W[wr * 128 + kt * 64 + c4 * 4];
                __half2 h0 = __floats2half2_rn(wv.x, wv.y);
                __half2 h1 = __floats2half2_rn(wv.z, wv.w);
                uint2 pk; pk.x = *(unsigned*)&h0; pk.y = *(unsigned*)&h1;
                *(uint2*)&Ws[wr][c4 * 4] = pk;
            }
        }
        __syncthreads();

#pragma unroll
        for (int k0 = 0; k0 < 64; k0 += 16) {
            wmma::fragment<wmma::matrix_a, 16, 16, 16, __half, wmma::row_major> a;
            wmma::load_matrix_sync(a, &Xs[warp * 16][k0], 72);
#pragma unroll
            for (int n0 = 0; n0 < 8; n0++) {
                wmma::fragment<wmma::matrix_b, 16, 16, 16, __half, wmma::col_major> b;
                wmma::load_matrix_sync(b, &Ws[n0 * 16][k0], 72);
                wmma::mma_sync(c[n0], a, b, c[n0]);
            }
        }
        __syncthreads();
    }

    int r  = lane >> 1;
    int cg = (lane & 1) * 8;
    int gr = row0 + warp * 16 + r;
#pragma unroll
    for (int n0 = 0; n0 < 8; n0++) {
        wmma::store_matrix_sync(&Stage[warp][0][0], c[n0], 20, wmma::mem_row_major);
        __syncwarp();
        if (gr < NN) {
            const float* src = &Stage[warp][r][cg];
            __half2 h0 = __floats2half2_rn(src[0], src[1]);
            __half2 h1 = __floats2half2_rn(src[2], src[3]);
            __half2 h2 = __floats2half2_rn(src[4], src[5]);
            __half2 h3 = __floats2half2_rn(src[6], src[7]);
            uint4 pk;
            pk.x = *(unsigned*)&h0; pk.y = *(unsigned*)&h1;
            pk.z = *(unsigned*)&h2; pk.w = *(unsigned*)&h3;
            *(uint4*)&g_H[gr * 128 + n0 * 16 + cg] = pk;
        }
        __syncwarp();
    }
}

// ---------------------------------------------------------------------------
// Single-kernel exclusive scan with parallel-lookback (49 co-resident blocks).
// ---------------------------------------------------------------------------
__global__ void __launch_bounds__(SCAN_BS) k_scan() {
    __shared__ int wsum[32];
    __shared__ int pred[64];
    __shared__ int spref;

    int t = threadIdx.x;
    int lane = t & 31;
    int wid = t >> 5;
    int i = blockIdx.x * SCAN_BS + t;
    int v = (i < NN) ? g_cnt[i] : 0;

    int x = v;
#pragma unroll
    for (int o = 1; o < 32; o <<= 1) {
        int u = __shfl_up_sync(0xffffffffu, x, o);
        if (lane >= o) x += u;
    }
    if (lane == 31) wsum[wid] = x;
    __syncthreads();
    if (wid == 0) {
        int y = wsum[lane];
#pragma unroll
        for (int o = 1; o < 32; o <<= 1) {
            int u = __shfl_up_sync(0xffffffffu, y, o);
            if (lane >= o) y += u;
        }
        wsum[lane] = y;
    }
    __syncthreads();

    int incl = x + (wid ? wsum[wid - 1] : 0);
    int block_total = wsum[31];

    if (t == 0) atomicExch(&g_cnt[NN + blockIdx.x], block_total | FLAG);

    if (t < 64) pred[t] = 0;
    __syncthreads();
    if (t < blockIdx.x) {
        int val;
        do { val = atomicAdd(&g_cnt[NN + t], 0); } while (!(val & FLAG));
        pred[t] = val & ~FLAG;
    }
    __syncthreads();
    if (t == 0) {
        int run = 0;
        for (int b = 0; b < (int)blockIdx.x; b++) run += pred[b];
        spref = run;
    }
    __syncthreads();

    int excl = spref + incl - v;
    if (i < NN) g_row_start[i] = excl;
    if (i == NN) g_row_start[NN] = NE;
}

// ---------------------------------------------------------------------------
// Scatter: atomic-free, 8 edges/thread, 4B packed records
// (col u16 | fp16(val) u16), u8 ranks. pos = row_start[row] + rank.
// ---------------------------------------------------------------------------
__device__ __forceinline__ unsigned pack_edge(int col, float val) {
    return (unsigned)col |
           ((unsigned)__half_as_ushort(__float2half_rn(val)) << 16);
}

__global__ void __launch_bounds__(256) k_scatter(const float* __restrict__ vals,
                                                 const int* __restrict__ rows,
                                                 const int* __restrict__ cols) {
    int t = blockIdx.x * blockDim.x + threadIdx.x;
    int base = t * 8;
    if (base < NE) {
        int4   r0 = *(const int4*)&rows[base];
        int4   r1 = *(const int4*)&rows[base + 4];
        int4   c0 = *(const int4*)&cols[base];
        int4   c1 = *(const int4*)&cols[base + 4];
        float4 v0 = *(const float4*)&vals[base];
        float4 v1 = *(const float4*)&vals[base + 4];
        uint2  kk = *(const uint2*)&g_rank[base];
        g_edge[g_row_start[r0.x] + ( kk.x        & 0xFF)] = pack_edge(c0.x, v0.x);
        g_edge[g_row_start[r0.y] + ((kk.x >>  8) & 0xFF)] = pack_edge(c0.y, v0.y);
        g_edge[g_row_start[r0.z] + ((kk.x >> 16) & 0xFF)] = pack_edge(c0.z, v0.z);
        g_edge[g_row_start[r0.w] + ((kk.x >> 24)       )] = pack_edge(c0.w, v0.w);
        g_edge[g_row_start[r1.x] + ( kk.y        & 0xFF)] = pack_edge(c1.x, v1.x);
        g_edge[g_row_start[r1.y] + ((kk.y >>  8) & 0xFF)] = pack_edge(c1.y, v1.y);
        g_edge[g_row_start[r1.z] + ((kk.y >> 16) & 0xFF)] = pack_edge(c1.z, v1.z);
        g_edge[g_row_start[r1.w] + ((kk.y >> 24)       )] = pack_edge(c1.w, v1.w);
    }
}

// ---------------------------------------------------------------------------
// SpMM: warp per row, lane owns 4 fp16 features (8B gather via __ldcg),
// fp32 accum, 16B-vectorized streaming edge loads + 8-deep unroll.
// ---------------------------------------------------------------------------
__device__ __forceinline__ void acc_edge(float acc[4], unsigned pk,
                                         const __half* __restrict__ hb) {
    int   c = (int)(pk & 0xFFFFu);
    float v = __half2float(__ushort_as_half((unsigned short)(pk >> 16)));
    uint2 hp = __ldcg((const uint2*)(hb + c * F));
    float2 f0 = __half22float2(*(__half2*)&hp.x);
    float2 f1 = __half22float2(*(__half2*)&hp.y);
    acc[0] += v * f0.x; acc[1] += v * f0.y;
    acc[2] += v * f1.x; acc[3] += v * f1.y;
}

__global__ void __launch_bounds__(256) k_spmm(float* __restrict__ out) {
    int warp = (blockIdx.x * blockDim.x + threadIdx.x) >> 5;
    int lane = threadIdx.x & 31;
    if (warp >= NN) return;

    int s = g_row_start[warp];
    int e = g_row_start[warp + 1];
    const __half* hb = g_H + lane * 4;   // per-lane feature base

    float acc[4] = {0.f, 0.f, 0.f, 0.f};
    int i = s;

    while (i < e && (i & 3)) {
        acc_edge(acc, g_edge[i], hb);
        i++;
    }
    for (; i + 7 < e; i += 8) {
        uint4 ea = __ldcs((const uint4*)&g_edge[i]);
        uint4 eb = __ldcs((const uint4*)&g_edge[i + 4]);
        acc_edge(acc, ea.x, hb); acc_edge(acc, ea.y, hb);
        acc_edge(acc, ea.z, hb); acc_edge(acc, ea.w, hb);
        acc_edge(acc, eb.x, hb); acc_edge(acc, eb.y, hb);
        acc_edge(acc, eb.z, hb); acc_edge(acc, eb.w, hb);
    }
    for (; i + 3 < e; i += 4) {
        uint4 ea = __ldcs((const uint4*)&g_edge[i]);
        acc_edge(acc, ea.x, hb); acc_edge(acc, ea.y, hb);
        acc_edge(acc, ea.z, hb); acc_edge(acc, ea.w, hb);
    }
    for (; i < e; i++) acc_edge(acc, g_edge[i], hb);

    *(float4*)&out[warp * F + lane * 4] =
        make_float4(acc[0], acc[1], acc[2], acc[3]);
}

// ---------------------------------------------------------------------------
extern "C" void kernel_launch(void* const* d_in, const int* in_sizes, int n_in,
                              void* d_out, int out_size) {
    const float* X     = (const float*)d_in[0];
    const float* W     = (const float*)d_in[1];
    const float* Avals = (const float*)d_in[2];
    const int*   Arows = (const int*)d_in[3];
    const int*   Acols = (const int*)d_in[4];
    float* out = (float*)d_out;

    // zero edge counters + scan flags (capturable async memset)
    void* cnt_addr = nullptr;
    cudaGetSymbolAddress(&cnt_addr, g_cnt);
    cudaMemsetAsync(cnt_addr, 0, (NN + 64) * sizeof(int));

    // fused, role-striped: histogram(+rank) truly co-resident with HMMA GEMM
    k_fused<<<G_HIST + G_GEMM, 256>>>(X, W, Arows);

    // one-shot prefix scan -> row_start
    k_scan<<<SCAN_NB, SCAN_BS>>>();

    // atomic-free scatter-permute into 4B records
    k_scatter<<<(NE / 8 + 255) / 256, 256>>>(Avals, Arows, Acols);

    // SpMM: out = A @ H
    k_spmm<<<(NN * 32 + 255) / 256, 256>>>(out);
}